// round 10
// baseline (speedup 1.0000x reference)
#include <cuda_runtime.h>
#include <cuda_bf16.h>

#define NN 10000
#define EE 100000
#define W  32

typedef unsigned long long u64;

__device__ __forceinline__ u64 pk2(float x, float y) {
    u64 r; asm("mov.b64 %0,{%1,%2};" : "=l"(r) : "f"(x), "f"(y)); return r;
}
__device__ __forceinline__ void fma2(u64& d, u64 a, u64 b) {
    asm("fma.rn.f32x2 %0,%1,%2,%0;" : "+l"(d) : "l"(a), "l"(b));
}
__device__ __forceinline__ float2 up2(u64 v) {
    float2 f; asm("mov.b64 {%0,%1},%2;" : "=f"(f.x), "=f"(f.y) : "l"(v)); return f;
}
__device__ __forceinline__ u64 add2(u64 a, u64 b) {
    u64 r; asm("add.rn.f32x2 %0,%1,%2;" : "=l"(r) : "l"(a), "l"(b)); return r;
}

// ---------------- scratch ----------------
__device__ float g_h[NN * W];
__device__ float g_coord[NN * 3];
__device__ float g_G[(size_t)NN * 4096];   // G[n][i*128+c]
__device__ float g_W3p[32 * 4096];         // W3p[j][i*128+c] = ker_w3[c][i*32+j]
__device__ float g_Bh[NN * W];
__device__ float g_msum[NN * W];
__device__ float g_csum[NN * 3];
__device__ int   g_degi[NN];
__device__ int   g_cnt[NN];
__device__ int   g_offs[NN + 1];
__device__ int   g_cur[NN];
__device__ int   g_srow[EE];
__device__ int   g_scol[EE];
__device__ float g_sea[EE * 6];

// ---------------- setup ----------------

__global__ void k_init(const float* __restrict__ x, const float* __restrict__ coords,
                       const float* __restrict__ fc1w, const float* __restrict__ fc1b, int n) {
    int idx = blockIdx.x * blockDim.x + threadIdx.x;
    if (idx < n * W) {
        int node = idx >> 5, i = idx & 31;
        float acc = fc1b[i];
#pragma unroll
        for (int j = 0; j < 3; j++) acc += x[node * 3 + j] * fc1w[j * W + i];
        g_h[idx] = acc;
    }
    if (idx < n * 3) g_coord[idx] = coords[idx];
    if (idx < n) { g_cnt[idx] = 0; g_degi[idx] = 0; }
}

__global__ void k_w3p(const float* __restrict__ kw3) {
    int idx = blockIdx.x * blockDim.x + threadIdx.x;
    if (idx < 128 * 1024) {
        int c = idx >> 10, rem = idx & 1023, i = rem >> 5, j = rem & 31;
        g_W3p[j * 4096 + i * 128 + c] = kw3[idx];
    }
}

__global__ void k_hist(const int* __restrict__ ei, int e) {
    int idx = blockIdx.x * blockDim.x + threadIdx.x;
    if (idx < e) {
        atomicAdd(&g_cnt[ei[e + idx]], 1);
        atomicAdd(&g_degi[ei[idx]], 1);
    }
}

__global__ __launch_bounds__(1024) void k_scan(int n) {
    __shared__ int ts[1024];
    int tid = threadIdx.x;
    int per = (n + 1023) / 1024;
    int base = tid * per;
    int s = 0;
    for (int i = 0; i < per; i++) { int idx = base + i; if (idx < n) s += g_cnt[idx]; }
    ts[tid] = s;
    __syncthreads();
    for (int off = 1; off < 1024; off <<= 1) {
        int v = (tid >= off) ? ts[tid - off] : 0;
        __syncthreads();
        ts[tid] += v;
        __syncthreads();
    }
    int run = (tid > 0) ? ts[tid - 1] : 0;
    for (int i = 0; i < per; i++) {
        int idx = base + i;
        if (idx < n) { int cv = g_cnt[idx]; g_offs[idx] = run; g_cur[idx] = run; run += cv; }
    }
    if (tid == 1023) g_offs[n] = run;
}

__global__ void k_scatter(const int* __restrict__ ei, const float* __restrict__ ea, int e) {
    int idx = blockIdx.x * blockDim.x + threadIdx.x;
    if (idx >= e) return;
    int c = ei[e + idx];
    int p = atomicAdd(&g_cur[c], 1);
    g_srow[p] = ei[idx];
    g_scol[p] = c;
#pragma unroll
    for (int a = 0; a < 6; a++) g_sea[p * 6 + a] = ea[idx * 6 + a];
}

__global__ void k_zero_acc(int n) {
    int idx = blockIdx.x * blockDim.x + threadIdx.x;
    if (idx < n * W) g_msum[idx] = 0.0f;
    if (idx < n * 3) g_csum[idx] = 0.0f;
}

// ---------------- per-depth ----------------

__global__ __launch_bounds__(256) void k_G(int n) {
    __shared__ float hs[64 * 32];
    __shared__ float bs[32 * 128];
    const int tid = threadIdx.x;
    const int n0 = blockIdx.x * 64;
    const int q0 = blockIdx.y * 128;
    for (int i = tid; i < 64 * 32; i += 256) {
        int nn = i >> 5, j = i & 31;
        int node = n0 + nn;
        hs[i] = (node < n) ? g_h[node * 32 + j] : 0.0f;
    }
    for (int i = tid; i < 32 * 128; i += 256) {
        int j = i >> 7, q = i & 127;
        bs[i] = g_W3p[j * 4096 + q0 + q];
    }
    __syncthreads();
    const int ty = tid >> 5, tx = tid & 31;
    float4 acc[8];
#pragma unroll
    for (int r = 0; r < 8; r++) acc[r] = make_float4(0.f, 0.f, 0.f, 0.f);
#pragma unroll
    for (int j = 0; j < 32; j++) {
        float4 bv = *(const float4*)&bs[j * 128 + tx * 4];
#pragma unroll
        for (int r = 0; r < 8; r++) {
            float a = hs[(ty + 8 * r) * 32 + j];
            acc[r].x += a * bv.x; acc[r].y += a * bv.y;
            acc[r].z += a * bv.z; acc[r].w += a * bv.w;
        }
    }
#pragma unroll
    for (int r = 0; r < 8; r++) {
        int node = n0 + ty + 8 * r;
        if (node < n)
            *(float4*)&g_G[(size_t)node * 4096 + q0 + tx * 4] = acc[r];
    }
}

__global__ void k_Bh(const float* __restrict__ kb3, int n) {
    int idx = blockIdx.x * blockDim.x + threadIdx.x;
    if (idx >= n * W) return;
    int node = idx >> 5, i = idx & 31;
    float acc = 0.0f;
#pragma unroll
    for (int j = 0; j < 32; j++) acc += kb3[i * 32 + j] * g_h[node * 32 + j];
    g_Bh[idx] = acc;
}

// smem float offsets for k_edge
#define SW2P   0        // 8192: kw2 permuted [cc][lane*4+t]
#define SKW1   8192     // 448
#define SKB1   8640     // 64
#define SKB2P  8704     // 128 paired [lane*4+t]
#define SCM1P  8832     // 1024: cmw1 paired [i2][lane*2+p]
#define SCMB1  9856     // 32
#define SCMW2  9888     // 32
#define SK1D   9920     // 8*128 duplicated k1 pairs
#define SK2S   10944    // 8*128
#define SMS    11968    // 8*32
#define STOT   12224    // *4 = 48896 bytes

// warp-per-edge fused kernel; edges sorted by col => G[col] L1-resident
__global__ __launch_bounds__(256) void k_edge(const float* __restrict__ kw1,
                                              const float* __restrict__ kb1,
                                              const float* __restrict__ kw2,
                                              const float* __restrict__ kb2,
                                              const float* __restrict__ cmw1,
                                              const float* __restrict__ cmb1,
                                              const float* __restrict__ cmw2,
                                              int e) {
    extern __shared__ float sm[];
    const int tid = threadIdx.x, w = tid >> 5, lane = tid & 31;

    for (int i = tid; i < 8192; i += 256) {
        int cc = i >> 7, out = i & 127, t = out >> 5, ln = out & 31;
        sm[SW2P + cc * 128 + ln * 4 + t] = kw2[i];
    }
    for (int i = tid; i < 448; i += 256) sm[SKW1 + i] = kw1[i];
    if (tid < 64)  sm[SKB1 + tid] = kb1[tid];
    if (tid < 128) { int t = tid >> 5, ln = tid & 31; sm[SKB2P + ln * 4 + t] = kb2[tid]; }
    for (int i = tid; i < 1024; i += 256) {
        int i2 = i >> 6, r = i & 63, ln = r >> 1, p = r & 1;
        sm[SCM1P + i] = cmw1[(2 * i2 + p) * 32 + ln];
    }
    if (tid < 32) { sm[SCMB1 + tid] = cmb1[tid]; sm[SCMW2 + tid] = cmw2[tid]; }
    __syncthreads();

    float* k1d = sm + SK1D + w * 128;
    float* k2s = sm + SK2S + w * 128;
    float* msb = sm + SMS + w * 32;

    int chunk = (e + gridDim.x - 1) / gridDim.x;
    int lo = blockIdx.x * chunk;
    int hi = lo + chunk; if (hi > e) hi = e;

    for (int ed = lo + w; ed < hi; ed += 8) {
        const int r = g_srow[ed], v = g_scol[ed];
        float ccrd = (lane < 3) ? g_coord[v * 3 + lane] : 0.0f;
        float cdl  = (lane < 3) ? (g_coord[r * 3 + lane] - ccrd) : 0.0f;
        float d0 = __shfl_sync(0xffffffffu, cdl, 0);
        float d1 = __shfl_sync(0xffffffffu, cdl, 1);
        float d2 = __shfl_sync(0xffffffffu, cdl, 2);
        float rad = d0 * d0 + d1 * d1 + d2 * d2;

        // layer 1 (c = lane, lane+32)
        float k1a = sm[SKB1 + lane], k1b = sm[SKB1 + 32 + lane];
#pragma unroll
        for (int a = 0; a < 6; a++) {
            float sa = __ldg(&g_sea[ed * 6 + a]);
            k1a += sa * sm[SKW1 + a * 64 + lane];
            k1b += sa * sm[SKW1 + a * 64 + 32 + lane];
        }
        k1a += rad * sm[SKW1 + 384 + lane];
        k1b += rad * sm[SKW1 + 384 + 32 + lane];
        k1a = fmaxf(k1a, 0.0f); k1b = fmaxf(k1b, 0.0f);
        *(u64*)&k1d[lane * 2]      = pk2(k1a, k1a);
        *(u64*)&k1d[64 + lane * 2] = pk2(k1b, k1b);
        __syncwarp();

        // layer 2: outputs k2[t*32+lane], t=0..3, packed-pair accumulation
        ulonglong2 b0 = *(const ulonglong2*)&sm[SKB2P + lane * 4];
        u64 a01_0 = b0.x, a23_0 = b0.y;
        u64 zz = pk2(0.f, 0.f);
        u64 a01_1 = zz, a23_1 = zz;
#pragma unroll
        for (int cc = 0; cc < 64; cc += 2) {
            ulonglong2 kp = *(const ulonglong2*)&k1d[cc * 2];
            ulonglong2 w0 = *(const ulonglong2*)&sm[SW2P + cc * 128 + lane * 4];
            ulonglong2 w1 = *(const ulonglong2*)&sm[SW2P + (cc + 1) * 128 + lane * 4];
            fma2(a01_0, kp.x, w0.x); fma2(a23_0, kp.x, w0.y);
            fma2(a01_1, kp.y, w1.x); fma2(a23_1, kp.y, w1.y);
        }
        float2 f01 = up2(add2(a01_0, a01_1));
        float2 f23 = up2(add2(a23_0, a23_1));
        k2s[lane]      = fmaxf(f01.x, 0.0f);
        k2s[32 + lane] = fmaxf(f01.y, 0.0f);
        k2s[64 + lane] = fmaxf(f23.x, 0.0f);
        k2s[96 + lane] = fmaxf(f23.y, 0.0f);
        __syncwarp();

        // contraction: m[lane] = Bh[v,lane] + sum_c k2[c]*G[v][lane*128+c]
        const float* gb = g_G + (size_t)v * 4096 + lane * 128;
        u64 mac0 = zz, mac1 = zz;
#pragma unroll
        for (int c = 0; c < 128; c += 4) {
            ulonglong2 kp = *(const ulonglong2*)&k2s[c];
            ulonglong2 gp = *(const ulonglong2*)&gb[c];
            fma2(mac0, kp.x, gp.x);
            fma2(mac1, kp.y, gp.y);
        }
        float2 mf = up2(add2(mac0, mac1));
        float m = g_Bh[v * 32 + lane] + mf.x + mf.y;
        msb[lane] = m;
        __syncwarp();

        // phi = relu(m @ cm_w1 + cm_b1) @ cm_w2
        u64 t2a = zz, t2b = zz;
#pragma unroll
        for (int i2 = 0; i2 < 16; i2 += 2) {
            u64 mp0 = *(const u64*)&msb[i2 * 2];
            u64 mp1 = *(const u64*)&msb[i2 * 2 + 2];
            u64 wp0 = *(const u64*)&sm[SCM1P + i2 * 64 + lane * 2];
            u64 wp1 = *(const u64*)&sm[SCM1P + (i2 + 1) * 64 + lane * 2];
            fma2(t2a, mp0, wp0);
            fma2(t2b, mp1, wp1);
        }
        float2 tf = up2(add2(t2a, t2b));
        float tac = fmaxf(sm[SCMB1 + lane] + tf.x + tf.y, 0.0f);
        float ph = tac * sm[SCMW2 + lane];
#pragma unroll
        for (int o = 16; o; o >>= 1) ph += __shfl_xor_sync(0xffffffffu, ph, o);

        atomicAdd(&g_msum[r * 32 + lane], m);
        if (lane < 3) atomicAdd(&g_csum[r * 3 + lane], cdl * ph);
        __syncwarp();
    }
}

__global__ void k_update(int n) {
    int idx = blockIdx.x * blockDim.x + threadIdx.x;
    if (idx >= n * W) return;
    int node = idx >> 5, i = idx & 31;
    int d = g_degi[node];
    float inv = 1.0f / (float)(d > 1 ? d : 1);
    g_h[idx] = fmaxf(g_h[idx] + g_msum[idx] * inv, 0.0f);
    if (i < 3) g_coord[node * 3 + i] += g_csum[node * 3 + i] * inv;
}

__global__ __launch_bounds__(256) void k_out(const float* __restrict__ fw1,
                                             const float* __restrict__ fb1,
                                             const float* __restrict__ fw2,
                                             const float* __restrict__ fb2,
                                             float* __restrict__ dout, int n) {
    int gw = (blockIdx.x * blockDim.x + threadIdx.x) >> 5;
    int lane = threadIdx.x & 31;
    if (gw >= n) return;
    const int node = gw;
    float hm = g_h[node * 32 + lane];
    float t0 = fb1[lane], t1 = fb1[lane + 32];
#pragma unroll
    for (int i = 0; i < 32; i++) {
        float hh = __shfl_sync(0xffffffffu, hm, i);
        t0 += hh * fw1[i * 64 + lane];
        t1 += hh * fw1[i * 64 + lane + 32];
    }
    t0 = fmaxf(t0, 0.0f);
    t1 = fmaxf(t1, 0.0f);
    float part = t0 * fw2[lane] + t1 * fw2[32 + lane];
#pragma unroll
    for (int o = 16; o; o >>= 1) part += __shfl_xor_sync(0xffffffffu, part, o);
    if (lane == 0) dout[node] = part + fb2[0];
    if (lane < 3) dout[n + node * 3 + lane] = g_coord[node * 3 + lane];
}

// ---------------- host launcher ----------------
extern "C" void kernel_launch(void* const* d_in, const int* in_sizes, int n_in,
                              void* d_out, int out_size) {
    const float* x      = (const float*)d_in[0];
    const int*   ei     = (const int*)  d_in[1];
    const float* eattr  = (const float*)d_in[2];
    const float* coords = (const float*)d_in[3];
    const float* fc1w   = (const float*)d_in[4];
    const float* fc1b   = (const float*)d_in[5];
    const float* kw1    = (const float*)d_in[6];
    const float* kb1    = (const float*)d_in[7];
    const float* kw2    = (const float*)d_in[8];
    const float* kb2    = (const float*)d_in[9];
    const float* kw3    = (const float*)d_in[10];
    const float* kb3    = (const float*)d_in[11];
    const float* cmw1   = (const float*)d_in[12];
    const float* cmb1   = (const float*)d_in[13];
    const float* cmw2   = (const float*)d_in[14];
    const float* fw1    = (const float*)d_in[15];
    const float* fb1    = (const float*)d_in[16];
    const float* fw2    = (const float*)d_in[17];
    const float* fb2    = (const float*)d_in[18];
    float* dout = (float*)d_out;

    int n = in_sizes[0] / 3;   // 10000
    int e = in_sizes[1] / 2;   // 100000
    if (n > NN) n = NN;
    if (e > EE) e = EE;

    const int T = 256;
    int gn32 = (n * W + T - 1) / T;
    size_t smem_edge = (size_t)STOT * sizeof(float);
    cudaFuncSetAttribute(k_edge, cudaFuncAttributeMaxDynamicSharedMemorySize, (int)smem_edge);

    dim3 gG((n + 63) / 64, 32);
    const int gEdge = 592;

    // launch order: #4 is k_G (depth 0) so ncu -s/-c capture lands on it
    k_init<<<gn32, T>>>(x, coords, fc1w, fc1b, n);      // 1
    k_w3p<<<(128 * 1024 + T - 1) / T, T>>>(kw3);        // 2
    k_hist<<<(e + T - 1) / T, T>>>(ei, e);              // 3
    k_G<<<gG, 256>>>(n);                                // 4  <- profiled
    k_scan<<<1, 1024>>>(n);                             // 5
    k_scatter<<<(e + T - 1) / T, T>>>(ei, eattr, e);    // 6
    k_zero_acc<<<gn32, T>>>(n);                         // 7
    k_Bh<<<gn32, T>>>(kb3, n);                          // 8
    k_edge<<<gEdge, T, smem_edge>>>(kw1, kb1, kw2, kb2, cmw1, cmb1, cmw2, e); // 9
    k_update<<<gn32, T>>>(n);                           // 10

    for (int depth = 1; depth < 3; depth++) {
        k_zero_acc<<<gn32, T>>>(n);
        k_G<<<gG, 256>>>(n);
        k_Bh<<<gn32, T>>>(kb3, n);
        k_edge<<<gEdge, T, smem_edge>>>(kw1, kb1, kw2, kb2, cmw1, cmb1, cmw2, e);
        k_update<<<gn32, T>>>(n);
    }
    k_out<<<(n * 32 + T - 1) / T, T>>>(fw1, fb1, fw2, fb2, dout, n);
}

// round 13
// speedup vs baseline: 2.1208x; 2.1208x over previous
#include <cuda_runtime.h>
#include <cuda_bf16.h>

#define NN 10000
#define EE 100000
#define W  32
#define CHMAX 24576

typedef unsigned long long u64;

__device__ __forceinline__ u64 pk2(float x, float y) {
    u64 r; asm("mov.b64 %0,{%1,%2};" : "=l"(r) : "f"(x), "f"(y)); return r;
}
__device__ __forceinline__ void fma2(u64& d, u64 a, u64 b) {
    asm("fma.rn.f32x2 %0,%1,%2,%0;" : "+l"(d) : "l"(a), "l"(b));
}
__device__ __forceinline__ float2 up2(u64 v) {
    float2 f; asm("mov.b64 {%0,%1},%2;" : "=f"(f.x), "=f"(f.y) : "l"(v)); return f;
}
__device__ __forceinline__ u64 add2(u64 a, u64 b) {
    u64 r; asm("add.rn.f32x2 %0,%1,%2;" : "=l"(r) : "l"(a), "l"(b)); return r;
}

// ---------------- scratch ----------------
__device__ float g_h[NN * W];
__device__ float g_coord[NN * 3];
__device__ float g_G[(size_t)NN * 4096];   // G[n][c*32+i]  (c-major)
__device__ float g_W3p[32 * 4096];         // W3p[j][c*32+i] = ker_w3[c][i*32+j]
__device__ float g_Bh[NN * W];
__device__ float g_msum[NN * W];
__device__ float g_csum[NN * 3];
__device__ int   g_degi[NN];
__device__ int   g_cnt[NN];
__device__ int   g_offs[NN + 1];
__device__ int   g_cur[NN];
__device__ int   g_srow[EE];
__device__ int   g_scol[EE];
__device__ float g_sea[EE * 6];
__device__ float g_k2[(size_t)EE * 128];
__device__ int   g_chcnt[NN];
__device__ int   g_choffs[NN + 1];
__device__ int   g_chv[CHMAX], g_che[CHMAX], g_chc[CHMAX];
__device__ int   g_nch;

// ---------------- setup ----------------

__global__ void k_w3p(const float* __restrict__ kw3) {
    int idx = blockIdx.x * blockDim.x + threadIdx.x;
    if (idx < 128 * 1024) {
        int c = idx >> 10, rem = idx & 1023, i = rem >> 5, j = rem & 31;
        g_W3p[j * 4096 + c * 32 + i] = kw3[idx];
    }
}

__global__ void k_zero_hist(int n) {
    int idx = blockIdx.x * blockDim.x + threadIdx.x;
    if (idx < n) { g_cnt[idx] = 0; g_degi[idx] = 0; }
}

__global__ void k_init(const float* __restrict__ x, const float* __restrict__ coords,
                       const float* __restrict__ fc1w, const float* __restrict__ fc1b,
                       const int* __restrict__ ei, int n, int e) {
    int idx = blockIdx.x * blockDim.x + threadIdx.x;
    if (idx < n * W) {
        int node = idx >> 5, i = idx & 31;
        float acc = fc1b[i];
#pragma unroll
        for (int j = 0; j < 3; j++) acc += x[node * 3 + j] * fc1w[j * W + i];
        g_h[idx] = acc;
    }
    if (idx < n * 3) g_coord[idx] = coords[idx];
    if (idx < e) {
        atomicAdd(&g_cnt[ei[e + idx]], 1);
        atomicAdd(&g_degi[ei[idx]], 1);
    }
}

__global__ __launch_bounds__(1024) void k_scan(int n) {
    __shared__ int ts[1024];
    int tid = threadIdx.x;
    int per = (n + 1023) / 1024;
    int base = tid * per;
    int s = 0;
    for (int i = 0; i < per; i++) { int idx = base + i; if (idx < n) s += g_cnt[idx]; }
    ts[tid] = s;
    __syncthreads();
    for (int off = 1; off < 1024; off <<= 1) {
        int v = (tid >= off) ? ts[tid - off] : 0;
        __syncthreads();
        ts[tid] += v;
        __syncthreads();
    }
    int run = (tid > 0) ? ts[tid - 1] : 0;
    for (int i = 0; i < per; i++) {
        int idx = base + i;
        if (idx < n) { int cv = g_cnt[idx]; g_offs[idx] = run; g_cur[idx] = run; run += cv; }
    }
    if (tid == 1023) g_offs[n] = run;
}

__global__ void k_scatter(const int* __restrict__ ei, const float* __restrict__ ea, int e) {
    int idx = blockIdx.x * blockDim.x + threadIdx.x;
    if (idx >= e) return;
    int c = ei[e + idx];
    int p = atomicAdd(&g_cur[c], 1);
    g_srow[p] = ei[idx];
    g_scol[p] = c;
#pragma unroll
    for (int a = 0; a < 6; a++) g_sea[p * 6 + a] = ea[idx * 6 + a];
}

__global__ void k_chprep(int n) {
    int v = blockIdx.x * blockDim.x + threadIdx.x;
    if (v < n) {
        int d = g_offs[v + 1] - g_offs[v];
        g_chcnt[v] = (d + 7) >> 3;
    }
}

__global__ __launch_bounds__(1024) void k_chscan(int n) {
    __shared__ int ts[1024];
    int tid = threadIdx.x;
    int per = (n + 1023) / 1024;
    int base = tid * per;
    int s = 0;
    for (int i = 0; i < per; i++) { int idx = base + i; if (idx < n) s += g_chcnt[idx]; }
    ts[tid] = s;
    __syncthreads();
    for (int off = 1; off < 1024; off <<= 1) {
        int v = (tid >= off) ? ts[tid - off] : 0;
        __syncthreads();
        ts[tid] += v;
        __syncthreads();
    }
    int run = (tid > 0) ? ts[tid - 1] : 0;
    for (int i = 0; i < per; i++) {
        int idx = base + i;
        if (idx < n) { int cv = g_chcnt[idx]; g_choffs[idx] = run; run += cv; }
    }
    if (tid == 1023) { g_choffs[n] = run; g_nch = run; }
}

__global__ void k_chfill(int n) {
    int v = blockIdx.x * blockDim.x + threadIdx.x;
    if (v >= n) return;
    int base = g_choffs[v], nc = g_chcnt[v];
    int s0 = g_offs[v], d = g_offs[v + 1] - s0;
    for (int k = 0; k < nc; k++) {
        g_chv[base + k] = v;
        g_che[base + k] = s0 + 8 * k;
        int rem = d - 8 * k;
        g_chc[base + k] = rem > 8 ? 8 : rem;
    }
}

__global__ void k_zero_acc(int n) {
    int idx = blockIdx.x * blockDim.x + threadIdx.x;
    if (idx < n * W) g_msum[idx] = 0.0f;
    if (idx < n * 3) g_csum[idx] = 0.0f;
}

// ---------------- per-depth ----------------

// edge MLP (layers 1+2) as a 64-edge x 128-col GEMM tile per block -> g_k2
#define MW2S 0        // 8192
#define MK1S 8192     // 64*65 = 4160
#define MEAS 12352    // 64*9 = 576
#define MW1S 12928    // 448
#define MB1S 13376    // 64
#define MTOT 13440    // *4 = 53760 bytes
__global__ __launch_bounds__(256, 3) void k_mlp(const float* __restrict__ kw1,
                                                const float* __restrict__ kb1,
                                                const float* __restrict__ kw2,
                                                const float* __restrict__ kb2, int e) {
    extern __shared__ float sm[];
    const int tid = threadIdx.x;
    const int e0 = blockIdx.x * 64;

    for (int i = tid; i < 8192; i += 256) sm[MW2S + i] = kw2[i];
    for (int i = tid; i < 448; i += 256)  sm[MW1S + i] = kw1[i];
    if (tid < 64) sm[MB1S + tid] = kb1[tid];
    // stage edge_attr (FIX: strided loop, block has only 256 threads)
    for (int i = tid; i < 384; i += 256) {
        int ed = i / 6, a = i - ed * 6;
        sm[MEAS + ed * 9 + a] = (e0 + ed < e) ? g_sea[(size_t)(e0 + ed) * 6 + a] : 0.0f;
    }
    // radial as 7th attr
    if (tid < 64) {
        float rad = 0.0f;
        if (e0 + tid < e) {
            int r = g_srow[e0 + tid], c = g_scol[e0 + tid];
#pragma unroll
            for (int d = 0; d < 3; d++) {
                float dd = g_coord[r * 3 + d] - g_coord[c * 3 + d];
                rad += dd * dd;
            }
        }
        sm[MEAS + tid * 9 + 6] = rad;
    }
    __syncthreads();

    // layer 1: k1[64][64]
    {
        int ed = tid >> 2, q = tid & 3;
        float ea[7];
#pragma unroll
        for (int a = 0; a < 7; a++) ea[a] = sm[MEAS + ed * 9 + a];
#pragma unroll
        for (int j = 0; j < 16; j++) {
            int c = q * 16 + j;
            float acc = sm[MB1S + c];
#pragma unroll
            for (int a = 0; a < 7; a++) acc += ea[a] * sm[MW1S + a * 64 + c];
            sm[MK1S + ed * 65 + c] = fmaxf(acc, 0.0f);
        }
    }
    __syncthreads();

    // layer 2 GEMM: 64x128 = K1[64x64] @ W2[64x128] + b2, relu
    const int ty = tid >> 5, tx = tid & 31;
    float4 bb = *(const float4*)&kb2[tx * 4];
    float4 acc[8];
#pragma unroll
    for (int r = 0; r < 8; r++) acc[r] = bb;
#pragma unroll
    for (int j = 0; j < 64; j++) {
        float4 bv = *(const float4*)&sm[MW2S + j * 128 + tx * 4];
#pragma unroll
        for (int r = 0; r < 8; r++) {
            float a = sm[MK1S + (ty + 8 * r) * 65 + j];
            acc[r].x += a * bv.x; acc[r].y += a * bv.y;
            acc[r].z += a * bv.z; acc[r].w += a * bv.w;
        }
    }
#pragma unroll
    for (int r = 0; r < 8; r++) {
        int ed = e0 + ty + 8 * r;
        if (ed < e) {
            float4 o = acc[r];
            o.x = fmaxf(o.x, 0.f); o.y = fmaxf(o.y, 0.f);
            o.z = fmaxf(o.z, 0.f); o.w = fmaxf(o.w, 0.f);
            *(float4*)&g_k2[(size_t)ed * 128 + tx * 4] = o;
        }
    }
}

// G[n][c*32+i] = sum_j h[n][j] * W3p[j][c*32+i]
__global__ __launch_bounds__(256, 3) void k_G(int n) {
    __shared__ float hs[64 * 32];
    __shared__ float bs[32 * 128];
    const int tid = threadIdx.x;
    const int n0 = blockIdx.x * 64;
    const int q0 = blockIdx.y * 128;
    for (int i = tid; i < 64 * 32; i += 256) {
        int nn = i >> 5, j = i & 31;
        int node = n0 + nn;
        hs[i] = (node < n) ? g_h[node * 32 + j] : 0.0f;
    }
    for (int i = tid; i < 32 * 128; i += 256) {
        int j = i >> 7, q = i & 127;
        bs[i] = g_W3p[j * 4096 + q0 + q];
    }
    __syncthreads();
    const int ty = tid >> 5, tx = tid & 31;
    float4 acc[8];
#pragma unroll
    for (int r = 0; r < 8; r++) acc[r] = make_float4(0.f, 0.f, 0.f, 0.f);
#pragma unroll
    for (int j = 0; j < 32; j++) {
        float4 bv = *(const float4*)&bs[j * 128 + tx * 4];
#pragma unroll
        for (int r = 0; r < 8; r++) {
            float a = hs[(ty + 8 * r) * 32 + j];
            acc[r].x += a * bv.x; acc[r].y += a * bv.y;
            acc[r].z += a * bv.z; acc[r].w += a * bv.w;
        }
    }
#pragma unroll
    for (int r = 0; r < 8; r++) {
        int node = n0 + ty + 8 * r;
        if (node < n)
            *(float4*)&g_G[(size_t)node * 4096 + q0 + tx * 4] = acc[r];
    }
}

__global__ void k_Bh(const float* __restrict__ kb3, int n) {
    int idx = blockIdx.x * blockDim.x + threadIdx.x;
    if (idx >= n * W) return;
    int node = idx >> 5, i = idx & 31;
    float acc = 0.0f;
#pragma unroll
    for (int j = 0; j < 32; j++) acc += kb3[i * 32 + j] * g_h[node * 32 + j];
    g_Bh[idx] = acc;
}

// chunked edge kernel: warp per <=8-edge same-col chunk
#define SCM1P 0       // 1024 (cmw1 pairs)
#define SCMB  1024    // 32
#define SCMW  1056    // 32
#define SK2P  1088    // 8 warps * 1024 floats (64 c-pairs x 8 edges as u64)
#define SMSB  9280    // 8 warps * 256
#define SETOT 11328   // *4 = 45312 bytes
__global__ __launch_bounds__(256) void k_edge(const float* __restrict__ cmw1,
                                              const float* __restrict__ cmb1,
                                              const float* __restrict__ cmw2) {
    extern __shared__ float sm[];
    const int tid = threadIdx.x, w = tid >> 5, lane = tid & 31;

    for (int i = tid; i < 1024; i += 256) {
        int i2 = i >> 6, r = i & 63, ln = r >> 1, p = r & 1;
        sm[SCM1P + i] = cmw1[(2 * i2 + p) * 32 + ln];
    }
    if (tid < 32) { sm[SCMB + tid] = cmb1[tid]; sm[SCMW + tid] = cmw2[tid]; }
    __syncthreads();

    u64* K2 = (u64*)(sm + SK2P + w * 1024);   // [c2][s] : c2*8+s
    float* msb = sm + SMSB + w * 256;
    const u64 zz = pk2(0.f, 0.f);

    const int TW = gridDim.x * 8;
    const int nch = g_nch;
    for (int ci = blockIdx.x * 8 + w; ci < nch; ci += TW) {
        const int v = g_chv[ci], e0 = g_che[ci], cnt = g_chc[ci];

        // transpose k2 rows into K2 (edge-pairs packed per c)
        {
            int s = lane >> 2, f = lane & 3;
            bool valid = (s < cnt);
#pragma unroll
            for (int t = 0; t < 8; t++) {
                int cb = (t * 4 + f) * 4;
                float4 vv = valid ? *(const float4*)&g_k2[(size_t)(e0 + s) * 128 + cb]
                                  : make_float4(0.f, 0.f, 0.f, 0.f);
                K2[(cb >> 1) * 8 + s]       = pk2(vv.x, vv.y);
                K2[((cb >> 1) + 1) * 8 + s] = pk2(vv.z, vv.w);
            }
        }
        int rl = (lane < cnt) ? g_srow[e0 + lane] : 0;
        float cv = (lane < 3) ? g_coord[v * 3 + lane] : 0.0f;
        float bh = g_Bh[v * 32 + lane];
        __syncwarp();

        // contraction: mm[s] += k2pair[c2][s] * (G[v][c*32+l], G[v][(c+1)*32+l])
        const float* gB = g_G + (size_t)v * 4096;
        u64 mm[8];
#pragma unroll
        for (int s = 0; s < 8; s++) mm[s] = zz;
        float ga = gB[lane], gb = gB[32 + lane];
#pragma unroll 4
        for (int c2 = 0; c2 < 64; c2++) {
            u64 gg = pk2(ga, gb);
            if (c2 < 63) { ga = gB[(c2 + 1) * 64 + lane]; gb = gB[(c2 + 1) * 64 + 32 + lane]; }
#pragma unroll
            for (int s = 0; s < 8; s++) fma2(mm[s], K2[c2 * 8 + s], gg);
        }
        float mreg[8];
#pragma unroll
        for (int s = 0; s < 8; s++) {
            float2 f2 = up2(mm[s]);
            mreg[s] = f2.x + f2.y + bh;
            msb[s * 32 + lane] = mreg[s];
        }
        __syncwarp();

        // per-edge phi + scatter
        for (int s = 0; s < cnt; s++) {
            u64 ta = zz, tb = zz;
#pragma unroll
            for (int i2 = 0; i2 < 16; i2 += 2) {
                u64 mp0 = *(const u64*)&msb[s * 32 + i2 * 2];
                u64 mp1 = *(const u64*)&msb[s * 32 + i2 * 2 + 2];
                u64 wp0 = *(const u64*)&sm[SCM1P + i2 * 64 + lane * 2];
                u64 wp1 = *(const u64*)&sm[SCM1P + (i2 + 1) * 64 + lane * 2];
                fma2(ta, mp0, wp0);
                fma2(tb, mp1, wp1);
            }
            float2 tf = up2(add2(ta, tb));
            float tac = fmaxf(sm[SCMB + lane] + tf.x + tf.y, 0.0f);
            float ph = tac * sm[SCMW + lane];
#pragma unroll
            for (int o = 16; o; o >>= 1) ph += __shfl_xor_sync(0xffffffffu, ph, o);

            int r = __shfl_sync(0xffffffffu, rl, s);
            atomicAdd(&g_msum[r * 32 + lane], mreg[s]);
            if (lane < 3) {
                float cdl = g_coord[r * 3 + lane] - cv;
                atomicAdd(&g_csum[r * 3 + lane], cdl * ph);
            }
        }
        __syncwarp();
    }
}

__global__ void k_update(int n) {
    int idx = blockIdx.x * blockDim.x + threadIdx.x;
    if (idx >= n * W) return;
    int node = idx >> 5, i = idx & 31;
    int d = g_degi[node];
    float inv = 1.0f / (float)(d > 1 ? d : 1);
    g_h[idx] = fmaxf(g_h[idx] + g_msum[idx] * inv, 0.0f);
    if (i < 3) g_coord[node * 3 + i] += g_csum[node * 3 + i] * inv;
}

__global__ __launch_bounds__(256) void k_out(const float* __restrict__ fw1,
                                             const float* __restrict__ fb1,
                                             const float* __restrict__ fw2,
                                             const float* __restrict__ fb2,
                                             float* __restrict__ dout, int n) {
    int gw = (blockIdx.x * blockDim.x + threadIdx.x) >> 5;
    int lane = threadIdx.x & 31;
    if (gw >= n) return;
    const int node = gw;
    float hm = g_h[node * 32 + lane];
    float t0 = fb1[lane], t1 = fb1[lane + 32];
#pragma unroll
    for (int i = 0; i < 32; i++) {
        float hh = __shfl_sync(0xffffffffu, hm, i);
        t0 += hh * fw1[i * 64 + lane];
        t1 += hh * fw1[i * 64 + lane + 32];
    }
    t0 = fmaxf(t0, 0.0f);
    t1 = fmaxf(t1, 0.0f);
    float part = t0 * fw2[lane] + t1 * fw2[32 + lane];
#pragma unroll
    for (int o = 16; o; o >>= 1) part += __shfl_xor_sync(0xffffffffu, part, o);
    if (lane == 0) dout[node] = part + fb2[0];
    if (lane < 3) dout[n + node * 3 + lane] = g_coord[node * 3 + lane];
}

// ---------------- host launcher ----------------
extern "C" void kernel_launch(void* const* d_in, const int* in_sizes, int n_in,
                              void* d_out, int out_size) {
    const float* x      = (const float*)d_in[0];
    const int*   ei     = (const int*)  d_in[1];
    const float* eattr  = (const float*)d_in[2];
    const float* coords = (const float*)d_in[3];
    const float* fc1w   = (const float*)d_in[4];
    const float* fc1b   = (const float*)d_in[5];
    const float* kw1    = (const float*)d_in[6];
    const float* kb1    = (const float*)d_in[7];
    const float* kw2    = (const float*)d_in[8];
    const float* kb2    = (const float*)d_in[9];
    const float* kw3    = (const float*)d_in[10];
    const float* kb3    = (const float*)d_in[11];
    const float* cmw1   = (const float*)d_in[12];
    const float* cmb1   = (const float*)d_in[13];
    const float* cmw2   = (const float*)d_in[14];
    const float* fw1    = (const float*)d_in[15];
    const float* fb1    = (const float*)d_in[16];
    const float* fw2    = (const float*)d_in[17];
    const float* fb2    = (const float*)d_in[18];
    float* dout = (float*)d_out;

    int n = in_sizes[0] / 3;   // 10000
    int e = in_sizes[1] / 2;   // 100000
    if (n > NN) n = NN;
    if (e > EE) e = EE;

    const int T = 256;
    int gn32 = (n * W + T - 1) / T;
    int gE   = (e + T - 1) / T;
    size_t smem_mlp  = (size_t)MTOT  * sizeof(float);
    size_t smem_edge = (size_t)SETOT * sizeof(float);
    cudaFuncSetAttribute(k_mlp,  cudaFuncAttributeMaxDynamicSharedMemorySize, (int)smem_mlp);
    cudaFuncSetAttribute(k_edge, cudaFuncAttributeMaxDynamicSharedMemorySize, (int)smem_edge);

    dim3 gG((n + 63) / 64, 32);
    int gMlp  = (e + 63) / 64;
    int gEdge = 592;

    k_w3p<<<(128 * 1024 + T - 1) / T, T>>>(kw3);                 // 1
    k_zero_hist<<<(n + T - 1) / T, T>>>(n);                       // 2
    k_init<<<gn32, T>>>(x, coords, fc1w, fc1b, ei, n, e);         // 3
    k_G<<<gG, 256>>>(n);                                          // 4 <- profiled
    k_scan<<<1, 1024>>>(n);                                       // 5
    k_scatter<<<gE, T>>>(ei, eattr, e);                           // 6
    k_chprep<<<(n + T - 1) / T, T>>>(n);                          // 7
    k_chscan<<<1, 1024>>>(n);                                     // 8
    k_chfill<<<(n + T - 1) / T, T>>>(n);                          // 9

    for (int depth = 0; depth < 3; depth++) {
        if (depth > 0) k_G<<<gG, 256>>>(n);
        k_mlp<<<gMlp, T, smem_mlp>>>(kw1, kb1, kw2, kb2, e);
        k_zero_acc<<<gn32, T>>>(n);
        k_Bh<<<gn32, T>>>(kb3, n);
        k_edge<<<gEdge, T, smem_edge>>>(cmw1, cmb1, cmw2);
        k_update<<<gn32, T>>>(n);
    }
    k_out<<<(n * 32 + T - 1) / T, T>>>(fw1, fb1, fw2, fb2, dout, n);
}